// round 14
// baseline (speedup 1.0000x reference)
#include <cuda_runtime.h>
#include <cuda_fp16.h>
#include <stdint.h>

#define LP    4
#define ENC   32
#define FEAT  64
#define D3    64
#define NBLK  296
#define WARPS 8
#define THREADS (WARPS * 32)
#define ZROWS 100000

typedef unsigned long long u64;

// X rows (PE only, 32 fp16 = 64 B): stride 80 B (20 words)
#define XSTRIDE_B 80
// W rows: 64 fp16 + pad -> stride 144 B (36 words)
#define WSTRIDE_B 144
// raw rows: 128 B fp16 feat + 16 B pos + pad -> stride 176 B (44 words; conflict-free)
#define RAWF_STRIDE 176

// ---- main-kernel smem layout (bytes) ----
#define OFF_W1P  0
#define OFF_B1P  512
#define OFF_WM2P 640
#define OFF_YBP  896
#define OFF_BM2  1152
#define OFF_WH   1280                                  // 96*144 = 13824
#define OFF_XH   (OFF_WH + 96 * WSTRIDE_B)             // 15104; 256*80 = 20480
#define OFF_RAWF (OFF_XH + THREADS * XSTRIDE_B)        // 35584; 256*176 = 45056
#define SMEM_TOTAL (OFF_RAWF + THREADS * RAWF_STRIDE)  // 80640 (x2 = 161 KB/SM)

__device__ __half g_feat16[(size_t)ZROWS * FEAT];      // node_feat rounded to fp16

// ---------------- helpers ----------------
__device__ __forceinline__ uint32_t smem_u32(const void* p) {
    uint32_t a;
    asm("{ .reg .u64 t; cvta.to.shared.u64 t, %1; cvt.u32.u64 %0, t; }" : "=r"(a) : "l"(p));
    return a;
}
__device__ __forceinline__ u64 pack2(float lo, float hi) {
    u64 r; asm("mov.b64 %0, {%1, %2};" : "=l"(r) : "f"(lo), "f"(hi)); return r;
}
__device__ __forceinline__ void unpack2(float& lo, float& hi, u64 v) {
    asm("mov.b64 {%0, %1}, %2;" : "=f"(lo), "=f"(hi) : "l"(v));
}
__device__ __forceinline__ u64 ffma2(u64 a, u64 b, u64 c) {
    u64 d; asm("fma.rn.f32x2 %0, %1, %2, %3;" : "=l"(d) : "l"(a), "l"(b), "l"(c)); return d;
}
#define LDSM_X4(r0, r1, r2, r3, a) \
    asm volatile("ldmatrix.sync.aligned.m8n8.x4.shared.b16 {%0,%1,%2,%3}, [%4];" \
                 : "=r"(r0), "=r"(r1), "=r"(r2), "=r"(r3) : "r"(a))
#define LDSM_X4_T(r0, r1, r2, r3, a) \
    asm volatile("ldmatrix.sync.aligned.m8n8.x4.trans.shared.b16 {%0,%1,%2,%3}, [%4];" \
                 : "=r"(r0), "=r"(r1), "=r"(r2), "=r"(r3) : "r"(a))
#define MMA16816H(d, a0, a1, a2, a3, b0, b1) \
    asm volatile("mma.sync.aligned.m16n8k16.row.col.f32.f16.f16.f32 " \
                 "{%0,%1,%2,%3}, {%4,%5,%6,%7}, {%8,%9}, {%0,%1,%2,%3};" \
                 : "+f"((d)[0]), "+f"((d)[1]), "+f"((d)[2]), "+f"((d)[3]) \
                 : "r"(a0), "r"(a1), "r"(a2), "r"(a3), "r"(b0), "r"(b1))
#define CP_ASYNC16(dst, src) \
    asm volatile("cp.async.cg.shared.global [%0], [%1], 16;" :: "r"(dst), "l"(src) : "memory")
#define CP_COMMIT() asm volatile("cp.async.commit_group;" ::: "memory")
#define CP_WAIT0()  asm volatile("cp.async.wait_group 0;" ::: "memory")

__device__ __forceinline__ unsigned pack_h2(float a, float b) {
    __half2 h2 = __floats2half2_rn(a, b);
    return *(unsigned*)&h2;
}

// ---------------------------------------------------------------------------
// prep_f16: round node_feat to fp16 once (DRAM-bound)
__global__ __launch_bounds__(256)
void prep_f16(const float* __restrict__ nf) {
    const int total = ZROWS * FEAT / 4;
    for (int t = blockIdx.x * blockDim.x + threadIdx.x; t < total;
         t += gridDim.x * blockDim.x) {
        const float4 v = *(const float4*)(nf + 4 * (size_t)t);
        *(uint2*)((char*)g_feat16 + 8 * (size_t)t) =
            make_uint2(pack_h2(v.x, v.y), pack_h2(v.z, v.w));
    }
}

// ---------------------------------------------------------------------------
__global__ __launch_bounds__(THREADS, 2)
void neurtw_mma(const float* __restrict__ pos_table,
                const float* __restrict__ W1,
                const float* __restrict__ b1,
                const float* __restrict__ W2,
                const float* __restrict__ b2,
                const float* __restrict__ Wm1,
                const float* __restrict__ bm1,
                const float* __restrict__ Wm2,
                const float* __restrict__ bm2,
                const int*   __restrict__ key_idx,
                const int*   __restrict__ node_idx,
                float* __restrict__ out,
                int nrows, int ntiles) {
    extern __shared__ __align__(128) char smem[];
    const uint32_t sb = smem_u32(smem);
    const int tid = threadIdx.x, wid = tid >> 5, lane = tid & 31;

    u64*   sW1p  = (u64*)(smem + OFF_W1P);
    u64*   sb1p  = (u64*)(smem + OFF_B1P);
    u64*   sWm2p = (u64*)(smem + OFF_WM2P);
    u64*   sYbp  = (u64*)(smem + OFF_YBP);
    float* sbm2  = (float*)(smem + OFF_BM2);

    if (tid < 32) sWm2p[tid] = pack2(Wm2[2 * tid], Wm2[2 * tid + 1]);
    if (tid >= 32 && tid < 48) { int j = tid - 32; sb1p[j] = pack2(b1[2 * j], b1[2 * j + 1]); }
    if (tid == 48) *sbm2 = bm2[0];
    if (tid >= 64 && tid < 128) {
        int idx = tid - 64, r = idx >> 4, j = idx & 15;
        sW1p[r * 16 + j] = pack2(W1[r * ENC + 2 * j], W1[r * ENC + 2 * j + 1]);
    }
    // ybias = bm1 + b2 @ Wm1_top : threads 160..191 compute one pair each
    if (tid >= 160 && tid < 192) {
        int p = tid - 160;
        float s0 = bm1[2 * p], s1 = bm1[2 * p + 1];
        #pragma unroll
        for (int e = 0; e < ENC; e++) {
            s0 = fmaf(b2[e], Wm1[e * D3 + 2 * p],     s0);
            s1 = fmaf(b2[e], Wm1[e * D3 + 2 * p + 1], s1);
        }
        sYbp[p] = pack2(s0, s1);
    }
    // W rows 0..31 = A = W2 @ Wm1_top (fp32 fold, identical order to old prep_kernel)
    #pragma unroll
    for (int i = 0; i < 8; i++) {
        int t = tid * 8 + i;            // 0..2047
        int k = t >> 6, n = t & 63;
        float s = 0.f;
        #pragma unroll
        for (int e = 0; e < ENC; e++)
            s = fmaf(W2[k * ENC + e], Wm1[e * D3 + n], s);
        *(__half*)(smem + OFF_WH + k * WSTRIDE_B + n * 2) = __float2half_rn(s);
    }
    // W rows 32..95 = Wm1 bottom
    for (int t = tid; t < 64 * 64; t += THREADS) {
        int k = ENC + (t >> 6), n = t & 63;
        *(__half*)(smem + OFF_WH + k * WSTRIDE_B + n * 2) = __float2half_rn(Wm1[k * D3 + n]);
    }
    __syncthreads();

    // ---- per-lane constant addresses ----
    const int g = lane >> 2, q4 = lane & 3;
    const int a_row  = (lane & 7) + 8 * ((lane >> 3) & 1);
    const int a_colb = (lane >> 4) * 16;
    const uint32_t xh_base = sb + OFF_XH + (uint32_t)(wid * 32 + a_row) * XSTRIDE_B + a_colb;
    const uint32_t xf_base = sb + OFF_RAWF + (uint32_t)(wid * 32 + a_row) * RAWF_STRIDE + a_colb;
    const uint32_t b_off = (uint32_t)(((lane & 7) + 8 * ((lane >> 3) & 1)) * WSTRIDE_B
                                      + (lane >> 4) * 16);
    const uint32_t wh_base = sb + OFF_WH + b_off;

    const int rowgrp = lane >> 3;     // 0..3 staging row subgroup
    const int q8     = lane & 7;      // 16B chunk within 128B fp16 row
    const uint32_t rawf_wbase = sb + OFF_RAWF + (uint32_t)(wid * 32) * RAWF_STRIDE;

    const int gw0 = blockIdx.x * WARPS + wid;
    const int gwstride = NBLK * WARPS;

    // ---- prologue: stage first tile (pos + fp16 feat rows) ----
    int key_c = 0, nid_c = 0;
    if (gw0 < ntiles) {
        int rr = gw0 * 32 + lane; if (rr >= nrows) rr = 0;
        key_c = key_idx[rr]; nid_c = node_idx[rr];
        CP_ASYNC16(rawf_wbase + lane * RAWF_STRIDE + 128,
                   (const char*)(pos_table + (size_t)key_c * LP));
        #pragma unroll
        for (int i = 0; i < 8; i++) {
            const int riw = 4 * i + rowgrp;
            const int nidr = __shfl_sync(0xffffffffu, nid_c, riw);
            CP_ASYNC16(rawf_wbase + riw * RAWF_STRIDE + q8 * 16,
                       (const char*)(g_feat16 + (size_t)nidr * FEAT) + q8 * 16);
        }
        CP_COMMIT();
    }

    for (int tile = gw0; tile < ntiles; tile += gwstride) {
        CP_WAIT0();
        __syncwarp();

        // ========== phase 1: PE hidden layer -> XH fp16 ==========
        {
            const float4 e4 = *(const float4*)(smem + OFF_RAWF
                                  + (wid * 32 + lane) * RAWF_STRIDE + 128);
            const u64 ex = pack2(e4.x, e4.x), ey = pack2(e4.y, e4.y);
            const u64 ez = pack2(e4.z, e4.z), ew = pack2(e4.w, e4.w);
            unsigned hv[16];
            #pragma unroll
            for (int j = 0; j < 16; j++) {
                u64 s = sb1p[j];
                s = ffma2(ex, sW1p[0 * 16 + j], s);
                s = ffma2(ey, sW1p[1 * 16 + j], s);
                s = ffma2(ez, sW1p[2 * 16 + j], s);
                s = ffma2(ew, sW1p[3 * 16 + j], s);
                float lo, hi; unpack2(lo, hi, s);
                hv[j] = pack_h2(fmaxf(lo, 0.f), fmaxf(hi, 0.f));
            }
            char* xh = smem + OFF_XH + (wid * 32 + lane) * XSTRIDE_B;
            *(uint4*)(xh)      = make_uint4(hv[0], hv[1], hv[2],  hv[3]);
            *(uint4*)(xh + 16) = make_uint4(hv[4], hv[5], hv[6],  hv[7]);
            *(uint4*)(xh + 32) = make_uint4(hv[8], hv[9], hv[10], hv[11]);
            *(uint4*)(xh + 48) = make_uint4(hv[12],hv[13],hv[14], hv[15]);
        }
        __syncwarp();

        // ========== phase 2: single-pass fp16 MMA, K=96 (A via ldmatrix only) ==========
        float acc[2][8][4];
        #pragma unroll
        for (int mt = 0; mt < 2; mt++)
            #pragma unroll
            for (int nt = 0; nt < 8; nt++)
                #pragma unroll
                for (int c = 0; c < 4; c++) acc[mt][nt][c] = 0.f;

        #pragma unroll
        for (int kc = 0; kc < 6; kc++) {
            const uint32_t bkoff = (uint32_t)(kc * 16 * WSTRIDE_B);
            uint32_t ah[2][4];
            if (kc < 2) {      // PE columns from XH
                const uint32_t ao = (uint32_t)(kc * 32);
                LDSM_X4(ah[0][0], ah[0][1], ah[0][2], ah[0][3], xh_base + ao);
                LDSM_X4(ah[1][0], ah[1][1], ah[1][2], ah[1][3],
                        xh_base + 16 * XSTRIDE_B + ao);
            } else {           // feat columns from RAWF (fp16 staged)
                const uint32_t ao = (uint32_t)((kc - 2) * 32);
                LDSM_X4(ah[0][0], ah[0][1], ah[0][2], ah[0][3], xf_base + ao);
                LDSM_X4(ah[1][0], ah[1][1], ah[1][2], ah[1][3],
                        xf_base + 16 * RAWF_STRIDE + ao);
            }
            uint32_t bh[8][2];
            #pragma unroll
            for (int ng = 0; ng < 4; ng++) {
                uint32_t r0, r1, r2, r3;
                LDSM_X4_T(r0, r1, r2, r3, wh_base + bkoff + (uint32_t)(ng * 32));
                bh[2*ng][0] = r0; bh[2*ng][1] = r1; bh[2*ng+1][0] = r2; bh[2*ng+1][1] = r3;
            }
            #pragma unroll
            for (int mt = 0; mt < 2; mt++)
                #pragma unroll
                for (int nt = 0; nt < 8; nt++)
                    MMA16816H(acc[mt][nt], ah[mt][0], ah[mt][1], ah[mt][2], ah[mt][3],
                              bh[nt][0], bh[nt][1]);
        }
        __syncwarp();   // RAWF fully consumed by ldmatrix before restaging

        // ---- stage next tile (lands during epilogue + next phase 1) ----
        {
            const int nt2 = tile + gwstride;
            if (nt2 < ntiles) {
                int rr = nt2 * 32 + lane; if (rr >= nrows) rr = 0;
                key_c = key_idx[rr]; nid_c = node_idx[rr];
                CP_ASYNC16(rawf_wbase + lane * RAWF_STRIDE + 128,
                           (const char*)(pos_table + (size_t)key_c * LP));
                #pragma unroll
                for (int i = 0; i < 8; i++) {
                    const int riw = 4 * i + rowgrp;
                    const int nidr = __shfl_sync(0xffffffffu, nid_c, riw);
                    CP_ASYNC16(rawf_wbase + riw * RAWF_STRIDE + q8 * 16,
                               (const char*)(g_feat16 + (size_t)nidr * FEAT) + q8 * 16);
                }
                CP_COMMIT();
            }
        }

        // ========== phase 3: ybias + relu + Wm2 dot (packed), reduce, store ==========
        float zr[4] = {0.f, 0.f, 0.f, 0.f};
        #pragma unroll
        for (int nt = 0; nt < 8; nt++) {
            float y0, y1, w0, w1;
            unpack2(y0, y1, sYbp[nt * 4 + q4]);
            unpack2(w0, w1, sWm2p[nt * 4 + q4]);
            #pragma unroll
            for (int mt = 0; mt < 2; mt++) {
                zr[mt*2+0] = fmaf(fmaxf(acc[mt][nt][0] + y0, 0.f), w0, zr[mt*2+0]);
                zr[mt*2+0] = fmaf(fmaxf(acc[mt][nt][1] + y1, 0.f), w1, zr[mt*2+0]);
                zr[mt*2+1] = fmaf(fmaxf(acc[mt][nt][2] + y0, 0.f), w0, zr[mt*2+1]);
                zr[mt*2+1] = fmaf(fmaxf(acc[mt][nt][3] + y1, 0.f), w1, zr[mt*2+1]);
            }
        }
        #pragma unroll
        for (int o = 1; o < 4; o <<= 1) {
            #pragma unroll
            for (int r = 0; r < 4; r++)
                zr[r] += __shfl_xor_sync(0xffffffffu, zr[r], o);
        }
        if (q4 == 0) {
            const float bias = *sbm2;
            const int base = tile * 32;
            const int rows[4] = {g, g + 8, 16 + g, 24 + g};
            #pragma unroll
            for (int r = 0; r < 4; r++) {
                int orow = base + rows[r];
                if (orow < nrows) out[orow] = zr[r] + bias;
            }
        }
        __syncwarp();
    }
}

// ---------------------------------------------------------------------------
extern "C" void kernel_launch(void* const* d_in, const int* in_sizes, int n_in,
                              void* d_out, int out_size) {
    const float* pos_table = (const float*)d_in[0];
    const float* node_feat = (const float*)d_in[1];
    const float* W1        = (const float*)d_in[2];
    const float* b1        = (const float*)d_in[3];
    const float* W2        = (const float*)d_in[4];
    const float* b2        = (const float*)d_in[5];
    const float* Wm1       = (const float*)d_in[6];
    const float* bm1       = (const float*)d_in[7];
    const float* Wm2       = (const float*)d_in[8];
    const float* bm2       = (const float*)d_in[9];
    const int*   key_idx   = (const int*)d_in[10];
    const int*   node_idx  = (const int*)d_in[11];
    float* out = (float*)d_out;

    const int nrows  = out_size;
    const int ntiles = (nrows + 31) / 32;

    cudaFuncSetAttribute(neurtw_mma,
                         cudaFuncAttributeMaxDynamicSharedMemorySize, SMEM_TOTAL);

    prep_f16<<<NBLK, 256>>>(node_feat);

    neurtw_mma<<<NBLK, THREADS, SMEM_TOTAL>>>(pos_table, W1, b1, W2, b2, Wm1, bm1,
                                              Wm2, bm2, key_idx, node_idx, out,
                                              nrows, ntiles);
}

// round 15
// speedup vs baseline: 1.1146x; 1.1146x over previous
#include <cuda_runtime.h>
#include <cuda_fp16.h>
#include <stdint.h>

#define LP    4
#define ENC   32
#define FEAT  64
#define D3    64
#define NBLK  296
#define WARPS 8
#define THREADS (WARPS * 32)
#define ZROWS 100000

typedef unsigned long long u64;

// X rows (PE only, 32 fp16 = 64 B): stride 80 B (20 words)
#define XSTRIDE_B 80
// W rows: 64 fp16 + pad -> stride 144 B (36 words)
#define WSTRIDE_B 144
// raw rows: 128 B fp16 feat + 16 B pos + pad -> stride 176 B (44 words; conflict-free)
#define RAWF_STRIDE 176

// ---- main-kernel smem layout (bytes) ----
#define OFF_W1P  0
#define OFF_B1P  512
#define OFF_WM2P 640
#define OFF_YBP  896
#define OFF_BM2  1152
#define OFF_WH   1280                                  // 96*144 = 13824
#define OFF_XH   (OFF_WH + 96 * WSTRIDE_B)             // 15104; 256*80 = 20480
#define OFF_RAWF (OFF_XH + THREADS * XSTRIDE_B)        // 35584; 256*176 = 45056
#define SMEM_TOTAL (OFF_RAWF + THREADS * RAWF_STRIDE)  // 80640 (x2 = 161 KB/SM)

__device__ float  g_A[ENC * D3];
__device__ float  g_ybias[D3];
__device__ __half g_feat16[(size_t)ZROWS * FEAT];      // node_feat rounded to fp16

// ---------------- helpers ----------------
__device__ __forceinline__ uint32_t smem_u32(const void* p) {
    uint32_t a;
    asm("{ .reg .u64 t; cvta.to.shared.u64 t, %1; cvt.u32.u64 %0, t; }" : "=r"(a) : "l"(p));
    return a;
}
__device__ __forceinline__ u64 pack2(float lo, float hi) {
    u64 r; asm("mov.b64 %0, {%1, %2};" : "=l"(r) : "f"(lo), "f"(hi)); return r;
}
__device__ __forceinline__ void unpack2(float& lo, float& hi, u64 v) {
    asm("mov.b64 {%0, %1}, %2;" : "=f"(lo), "=f"(hi) : "l"(v));
}
__device__ __forceinline__ u64 ffma2(u64 a, u64 b, u64 c) {
    u64 d; asm("fma.rn.f32x2 %0, %1, %2, %3;" : "=l"(d) : "l"(a), "l"(b), "l"(c)); return d;
}
#define LDSM_X4(r0, r1, r2, r3, a) \
    asm volatile("ldmatrix.sync.aligned.m8n8.x4.shared.b16 {%0,%1,%2,%3}, [%4];" \
                 : "=r"(r0), "=r"(r1), "=r"(r2), "=r"(r3) : "r"(a))
#define LDSM_X4_T(r0, r1, r2, r3, a) \
    asm volatile("ldmatrix.sync.aligned.m8n8.x4.trans.shared.b16 {%0,%1,%2,%3}, [%4];" \
                 : "=r"(r0), "=r"(r1), "=r"(r2), "=r"(r3) : "r"(a))
#define MMA16816H(d, a0, a1, a2, a3, b0, b1) \
    asm volatile("mma.sync.aligned.m16n8k16.row.col.f32.f16.f16.f32 " \
                 "{%0,%1,%2,%3}, {%4,%5,%6,%7}, {%8,%9}, {%0,%1,%2,%3};" \
                 : "+f"((d)[0]), "+f"((d)[1]), "+f"((d)[2]), "+f"((d)[3]) \
                 : "r"(a0), "r"(a1), "r"(a2), "r"(a3), "r"(b0), "r"(b1))
#define CP_ASYNC16(dst, src) \
    asm volatile("cp.async.cg.shared.global [%0], [%1], 16;" :: "r"(dst), "l"(src) : "memory")
#define CP_COMMIT() asm volatile("cp.async.commit_group;" ::: "memory")
#define CP_WAIT0()  asm volatile("cp.async.wait_group 0;" ::: "memory")

__device__ __forceinline__ unsigned pack_h2(float a, float b) {
    __half2 h2 = __floats2half2_rn(a, b);
    return *(unsigned*)&h2;
}

// ---------------------------------------------------------------------------
// prep_all: block 0 computes g_A / g_ybias (from smem-staged weights);
// blocks 1..NBLK-1 convert node_feat -> fp16 (DRAM-bound). Concurrent.
// ---------------------------------------------------------------------------
__global__ __launch_bounds__(256)
void prep_all(const float* __restrict__ nf,
              const float* __restrict__ W2,
              const float* __restrict__ Wm1,
              const float* __restrict__ b2,
              const float* __restrict__ bm1) {
    const int tid = threadIdx.x;
    if (blockIdx.x == 0) {
        __shared__ float sW2[ENC * ENC];     // 4 KB
        __shared__ float sM[ENC * D3];       // 8 KB (Wm1 top rows)
        for (int t = tid; t < ENC * ENC; t += 256) sW2[t] = W2[t];
        for (int t = tid; t < ENC * D3; t += 256) sM[t] = Wm1[t];
        __syncthreads();
        // identical accumulation order to original prep_kernel (e sequential)
        #pragma unroll
        for (int i = 0; i < 8; i++) {
            int t = tid + i * 256;           // 0..2047
            int k = t >> 6, j = t & 63;
            float s = 0.f;
            #pragma unroll
            for (int e = 0; e < ENC; e++)
                s = fmaf(sW2[k * ENC + e], sM[e * D3 + j], s);
            g_A[t] = s;
        }
        if (tid < D3) {
            float s = bm1[tid];
            #pragma unroll
            for (int e = 0; e < ENC; e++)
                s = fmaf(b2[e], sM[e * D3 + tid], s);
            g_ybias[tid] = s;
        }
    } else {
        const int total = ZROWS * FEAT / 4;
        for (int t = (blockIdx.x - 1) * 256 + tid; t < total;
             t += (gridDim.x - 1) * 256) {
            const float4 v = *(const float4*)(nf + 4 * (size_t)t);
            *(uint2*)((char*)g_feat16 + 8 * (size_t)t) =
                make_uint2(pack_h2(v.x, v.y), pack_h2(v.z, v.w));
        }
    }
}

// ---------------------------------------------------------------------------
__global__ __launch_bounds__(THREADS, 2)
void neurtw_mma(const float* __restrict__ pos_table,
                const float* __restrict__ W1,
                const float* __restrict__ b1,
                const float* __restrict__ Wm1,
                const float* __restrict__ Wm2,
                const float* __restrict__ bm2,
                const int*   __restrict__ key_idx,
                const int*   __restrict__ node_idx,
                float* __restrict__ out,
                int nrows, int ntiles) {
    extern __shared__ __align__(128) char smem[];
    const uint32_t sb = smem_u32(smem);
    const int tid = threadIdx.x, wid = tid >> 5, lane = tid & 31;

    u64*   sW1p  = (u64*)(smem + OFF_W1P);
    u64*   sb1p  = (u64*)(smem + OFF_B1P);
    u64*   sWm2p = (u64*)(smem + OFF_WM2P);
    u64*   sYbp  = (u64*)(smem + OFF_YBP);
    float* sbm2  = (float*)(smem + OFF_BM2);

    if (tid < 32) sWm2p[tid] = pack2(Wm2[2 * tid], Wm2[2 * tid + 1]);
    if (tid >= 32 && tid < 48) { int j = tid - 32; sb1p[j] = pack2(b1[2 * j], b1[2 * j + 1]); }
    if (tid == 48) *sbm2 = bm2[0];
    if (tid >= 64 && tid < 128) {
        int idx = tid - 64, r = idx >> 4, j = idx & 15;
        sW1p[r * 16 + j] = pack2(W1[r * ENC + 2 * j], W1[r * ENC + 2 * j + 1]);
    }
    if (tid >= 128 && tid < 160) {
        int p = tid - 128;
        sYbp[p] = pack2(g_ybias[2 * p], g_ybias[2 * p + 1]);
    }
    // stage W fp16: rows 0..31 g_A, 32..95 Wm1
    for (int t = tid; t < 96 * 64; t += THREADS) {
        int k = t >> 6, n = t & 63;
        float w = (k < ENC) ? g_A[k * D3 + n] : Wm1[k * D3 + n];
        *(__half*)(smem + OFF_WH + k * WSTRIDE_B + n * 2) = __float2half_rn(w);
    }
    __syncthreads();

    // ---- per-lane constant addresses ----
    const int g = lane >> 2, q4 = lane & 3;
    const int a_row  = (lane & 7) + 8 * ((lane >> 3) & 1);
    const int a_colb = (lane >> 4) * 16;
    const uint32_t xh_base = sb + OFF_XH + (uint32_t)(wid * 32 + a_row) * XSTRIDE_B + a_colb;
    const uint32_t xf_base = sb + OFF_RAWF + (uint32_t)(wid * 32 + a_row) * RAWF_STRIDE + a_colb;
    const uint32_t b_off = (uint32_t)(((lane & 7) + 8 * ((lane >> 3) & 1)) * WSTRIDE_B
                                      + (lane >> 4) * 16);
    const uint32_t wh_base = sb + OFF_WH + b_off;

    const int rowgrp = lane >> 3;     // 0..3 staging row subgroup
    const int q8     = lane & 7;      // 16B chunk within 128B fp16 row
    const uint32_t rawf_wbase = sb + OFF_RAWF + (uint32_t)(wid * 32) * RAWF_STRIDE;

    const int gw0 = blockIdx.x * WARPS + wid;
    const int gwstride = NBLK * WARPS;

    // ---- prologue: stage first tile (pos + fp16 feat rows) ----
    int key_c = 0, nid_c = 0;
    if (gw0 < ntiles) {
        int rr = gw0 * 32 + lane; if (rr >= nrows) rr = 0;
        key_c = key_idx[rr]; nid_c = node_idx[rr];
        CP_ASYNC16(rawf_wbase + lane * RAWF_STRIDE + 128,
                   (const char*)(pos_table + (size_t)key_c * LP));
        #pragma unroll
        for (int i = 0; i < 8; i++) {
            const int riw = 4 * i + rowgrp;
            const int nidr = __shfl_sync(0xffffffffu, nid_c, riw);
            CP_ASYNC16(rawf_wbase + riw * RAWF_STRIDE + q8 * 16,
                       (const char*)(g_feat16 + (size_t)nidr * FEAT) + q8 * 16);
        }
        CP_COMMIT();
    }

    for (int tile = gw0; tile < ntiles; tile += gwstride) {
        CP_WAIT0();
        __syncwarp();

        // ========== phase 1: PE hidden layer -> XH fp16 ==========
        {
            const float4 e4 = *(const float4*)(smem + OFF_RAWF
                                  + (wid * 32 + lane) * RAWF_STRIDE + 128);
            const u64 ex = pack2(e4.x, e4.x), ey = pack2(e4.y, e4.y);
            const u64 ez = pack2(e4.z, e4.z), ew = pack2(e4.w, e4.w);
            unsigned hv[16];
            #pragma unroll
            for (int j = 0; j < 16; j++) {
                u64 s = sb1p[j];
                s = ffma2(ex, sW1p[0 * 16 + j], s);
                s = ffma2(ey, sW1p[1 * 16 + j], s);
                s = ffma2(ez, sW1p[2 * 16 + j], s);
                s = ffma2(ew, sW1p[3 * 16 + j], s);
                float lo, hi; unpack2(lo, hi, s);
                hv[j] = pack_h2(fmaxf(lo, 0.f), fmaxf(hi, 0.f));
            }
            char* xh = smem + OFF_XH + (wid * 32 + lane) * XSTRIDE_B;
            *(uint4*)(xh)      = make_uint4(hv[0], hv[1], hv[2],  hv[3]);
            *(uint4*)(xh + 16) = make_uint4(hv[4], hv[5], hv[6],  hv[7]);
            *(uint4*)(xh + 32) = make_uint4(hv[8], hv[9], hv[10], hv[11]);
            *(uint4*)(xh + 48) = make_uint4(hv[12],hv[13],hv[14], hv[15]);
        }
        __syncwarp();

        // ========== phase 2: single-pass fp16 MMA, K=96 (A via ldmatrix only) ==========
        float acc[2][8][4];
        #pragma unroll
        for (int mt = 0; mt < 2; mt++)
            #pragma unroll
            for (int nt = 0; nt < 8; nt++)
                #pragma unroll
                for (int c = 0; c < 4; c++) acc[mt][nt][c] = 0.f;

        #pragma unroll
        for (int kc = 0; kc < 6; kc++) {
            const uint32_t bkoff = (uint32_t)(kc * 16 * WSTRIDE_B);
            uint32_t ah[2][4];
            if (kc < 2) {      // PE columns from XH
                const uint32_t ao = (uint32_t)(kc * 32);
                LDSM_X4(ah[0][0], ah[0][1], ah[0][2], ah[0][3], xh_base + ao);
                LDSM_X4(ah[1][0], ah[1][1], ah[1][2], ah[1][3],
                        xh_base + 16 * XSTRIDE_B + ao);
            } else {           // feat columns from RAWF (fp16 staged)
                const uint32_t ao = (uint32_t)((kc - 2) * 32);
                LDSM_X4(ah[0][0], ah[0][1], ah[0][2], ah[0][3], xf_base + ao);
                LDSM_X4(ah[1][0], ah[1][1], ah[1][2], ah[1][3],
                        xf_base + 16 * RAWF_STRIDE + ao);
            }
            uint32_t bh[8][2];
            #pragma unroll
            for (int ng = 0; ng < 4; ng++) {
                uint32_t r0, r1, r2, r3;
                LDSM_X4_T(r0, r1, r2, r3, wh_base + bkoff + (uint32_t)(ng * 32));
                bh[2*ng][0] = r0; bh[2*ng][1] = r1; bh[2*ng+1][0] = r2; bh[2*ng+1][1] = r3;
            }
            #pragma unroll
            for (int mt = 0; mt < 2; mt++)
                #pragma unroll
                for (int nt = 0; nt < 8; nt++)
                    MMA16816H(acc[mt][nt], ah[mt][0], ah[mt][1], ah[mt][2], ah[mt][3],
                              bh[nt][0], bh[nt][1]);
        }
        __syncwarp();   // RAWF fully consumed by ldmatrix before restaging

        // ---- stage next tile (lands during epilogue + next phase 1) ----
        {
            const int nt2 = tile + gwstride;
            if (nt2 < ntiles) {
                int rr = nt2 * 32 + lane; if (rr >= nrows) rr = 0;
                key_c = key_idx[rr]; nid_c = node_idx[rr];
                CP_ASYNC16(rawf_wbase + lane * RAWF_STRIDE + 128,
                           (const char*)(pos_table + (size_t)key_c * LP));
                #pragma unroll
                for (int i = 0; i < 8; i++) {
                    const int riw = 4 * i + rowgrp;
                    const int nidr = __shfl_sync(0xffffffffu, nid_c, riw);
                    CP_ASYNC16(rawf_wbase + riw * RAWF_STRIDE + q8 * 16,
                               (const char*)(g_feat16 + (size_t)nidr * FEAT) + q8 * 16);
                }
                CP_COMMIT();
            }
        }

        // ========== phase 3: ybias + relu + Wm2 dot (packed), reduce, store ==========
        float zr[4] = {0.f, 0.f, 0.f, 0.f};
        #pragma unroll
        for (int nt = 0; nt < 8; nt++) {
            float y0, y1, w0, w1;
            unpack2(y0, y1, sYbp[nt * 4 + q4]);
            unpack2(w0, w1, sWm2p[nt * 4 + q4]);
            #pragma unroll
            for (int mt = 0; mt < 2; mt++) {
                zr[mt*2+0] = fmaf(fmaxf(acc[mt][nt][0] + y0, 0.f), w0, zr[mt*2+0]);
                zr[mt*2+0] = fmaf(fmaxf(acc[mt][nt][1] + y1, 0.f), w1, zr[mt*2+0]);
                zr[mt*2+1] = fmaf(fmaxf(acc[mt][nt][2] + y0, 0.f), w0, zr[mt*2+1]);
                zr[mt*2+1] = fmaf(fmaxf(acc[mt][nt][3] + y1, 0.f), w1, zr[mt*2+1]);
            }
        }
        #pragma unroll
        for (int o = 1; o < 4; o <<= 1) {
            #pragma unroll
            for (int r = 0; r < 4; r++)
                zr[r] += __shfl_xor_sync(0xffffffffu, zr[r], o);
        }
        if (q4 == 0) {
            const float bias = *sbm2;
            const int base = tile * 32;
            const int rows[4] = {g, g + 8, 16 + g, 24 + g};
            #pragma unroll
            for (int r = 0; r < 4; r++) {
                int orow = base + rows[r];
                if (orow < nrows) out[orow] = zr[r] + bias;
            }
        }
        __syncwarp();
    }
}

// ---------------------------------------------------------------------------
extern "C" void kernel_launch(void* const* d_in, const int* in_sizes, int n_in,
                              void* d_out, int out_size) {
    const float* pos_table = (const float*)d_in[0];
    const float* node_feat = (const float*)d_in[1];
    const float* W1        = (const float*)d_in[2];
    const float* b1        = (const float*)d_in[3];
    const float* W2        = (const float*)d_in[4];
    const float* b2        = (const float*)d_in[5];
    const float* Wm1       = (const float*)d_in[6];
    const float* bm1       = (const float*)d_in[7];
    const float* Wm2       = (const float*)d_in[8];
    const float* bm2       = (const float*)d_in[9];
    const int*   key_idx   = (const int*)d_in[10];
    const int*   node_idx  = (const int*)d_in[11];
    float* out = (float*)d_out;

    const int nrows  = out_size;
    const int ntiles = (nrows + 31) / 32;

    cudaFuncSetAttribute(neurtw_mma,
                         cudaFuncAttributeMaxDynamicSharedMemorySize, SMEM_TOTAL);

    prep_all<<<NBLK, 256>>>(node_feat, W2, Wm1, b2, bm1);

    neurtw_mma<<<NBLK, THREADS, SMEM_TOTAL>>>(pos_table, W1, b1, Wm1,
                                              Wm2, bm2, key_idx, node_idx, out,
                                              nrows, ntiles);
}